// round 2
// baseline (speedup 1.0000x reference)
#include <cuda_runtime.h>
#include <math.h>

// Shapes
#define V_SZ 50257
#define E_SZ 512
#define H_SZ 1024
#define C_SZ 1024
#define S_SZ 2048
#define NRC 4               // row-chunks for wsum partials

// ---------------- scratch (device globals; no allocation allowed) -------------
__device__ __align__(16) float g_q[H_SZ];               // rnn_output
__device__ __align__(16) float g_u[3][C_SZ];            // W^T q per head
__device__            float g_bq[3];                    // b . q per head
__device__ __align__(16) float g_e[3][S_SZ];            // attention logits
__device__ __align__(16) float g_wpart[3][NRC][C_SZ];   // wsum row-chunk partials

// ---------------- helpers ------------------------------------------------------
__device__ __forceinline__ float warp_sum(float v) {
#pragma unroll
    for (int o = 16; o; o >>= 1) v += __shfl_xor_sync(0xffffffffu, v, o);
    return v;
}
__device__ __forceinline__ float warp_max(float v) {
#pragma unroll
    for (int o = 16; o; o >>= 1) v = fmaxf(v, __shfl_xor_sync(0xffffffffu, v, o));
    return v;
}
__device__ __forceinline__ float sigf(float x) { return 1.0f / (1.0f + expf(-x)); }
__device__ __forceinline__ float dot4(float4 w, float4 v) {
    return w.x * v.x + w.y * v.y + w.z * v.z + w.w * v.w;
}

// ---------------- K1/K2: fused LSTM gate GEMV + activation ---------------------
// Warp per h-index j: computes all 4 gate rows (i,f,g,o) then the activation.
// grid 128, block 256 (8 warps -> 8 j per block)
__global__ void k_gates_fused(const float* __restrict__ Wih, int lenA,
                              const float* __restrict__ Whh,
                              const float* __restrict__ bih, const float* __restrict__ bhh,
                              const float* __restrict__ xbase, const int* __restrict__ idx,
                              const float* __restrict__ hprev,
                              const float* __restrict__ cprev,
                              float* __restrict__ hout, float* __restrict__ cout,
                              int copy_q) {
    extern __shared__ float sh[];  // lenA + H floats
    const float* x = idx ? (xbase + (size_t)idx[0] * lenA) : xbase;
    const int tid = threadIdx.x;
    for (int i = tid; i < lenA; i += blockDim.x) sh[i] = x[i];
    for (int i = tid; i < H_SZ; i += blockDim.x) sh[lenA + i] = hprev[i];
    __syncthreads();

    const int j    = blockIdx.x * 8 + (tid >> 5);
    const int lane = tid & 31;
    const float4* x4 = (const float4*)sh;
    const float4* h4 = (const float4*)(sh + lenA);
    const int nA = lenA >> 2, nH = H_SZ >> 2;

    float acc[4];
#pragma unroll
    for (int gi = 0; gi < 4; gi++) {
        const float4* a = (const float4*)(Wih + (size_t)(gi * H_SZ + j) * lenA);
        const float4* b = (const float4*)(Whh + (size_t)(gi * H_SZ + j) * H_SZ);
        float s = 0.f;
#pragma unroll 4
        for (int i = lane; i < nA; i += 32) s += dot4(a[i], x4[i]);
#pragma unroll 4
        for (int i = lane; i < nH; i += 32) s += dot4(b[i], h4[i]);
        acc[gi] = s;
    }
#pragma unroll
    for (int gi = 0; gi < 4; gi++) acc[gi] = warp_sum(acc[gi]);

    if (lane == 0) {
        const float ig = sigf (acc[0] + bih[j]            + bhh[j]);
        const float fg = sigf (acc[1] + bih[H_SZ + j]     + bhh[H_SZ + j]);
        const float gg = tanhf(acc[2] + bih[2 * H_SZ + j] + bhh[2 * H_SZ + j]);
        const float og = sigf (acc[3] + bih[3 * H_SZ + j] + bhh[3 * H_SZ + j]);
        const float c = fg * cprev[j] + ig * gg;
        const float h = og * tanhf(c);
        cout[j] = c;
        hout[j] = h;
        if (copy_q) g_q[j] = h;
    }
}

// ---------------- K3: u = W^T q (+ bq in col-chunk 0) --------------------------
// grid dim3(8, 3): 8 column chunks of 128 cols, 3 heads. block 256.
__global__ void k_u(const float* __restrict__ WL,
                    const float* __restrict__ WR,
                    const float* __restrict__ WM,
                    const float* __restrict__ bL,
                    const float* __restrict__ bR,
                    const float* __restrict__ bM) {
    __shared__ float  shq[H_SZ];
    __shared__ float4 red4[8][32];
    __shared__ float  redb[32];
    const int hd = blockIdx.y;
    const float* W    = (hd == 0) ? WL : (hd == 1) ? WR : WM;
    const float* bias = (hd == 0) ? bL : (hd == 1) ? bR : bM;
    const int tid = threadIdx.x;
    for (int i = tid; i < H_SZ; i += 256) shq[i] = g_q[i];
    __syncthreads();

    const int lane = tid & 31, grp = tid >> 5;
    const int c4 = blockIdx.x * 32 + lane;         // float4 column index
    const float4* W4 = (const float4*)W;
    float4 acc = make_float4(0.f, 0.f, 0.f, 0.f);
#pragma unroll 8
    for (int r = grp; r < H_SZ; r += 8) {
        float4 w = W4[(size_t)r * (C_SZ >> 2) + c4];
        float qv = shq[r];
        acc.x += w.x * qv; acc.y += w.y * qv; acc.z += w.z * qv; acc.w += w.w * qv;
    }
    red4[grp][lane] = acc;
    __syncthreads();
    if (grp == 0) {
        float4 t = red4[0][lane];
#pragma unroll
        for (int k = 1; k < 8; k++) {
            float4 p = red4[k][lane];
            t.x += p.x; t.y += p.y; t.z += p.z; t.w += p.w;
        }
        ((float4*)g_u[hd])[blockIdx.x * 32 + lane] = t;
    }

    // bq = bias . q, only in col-chunk 0 (deterministic fixed-order reduce)
    if (blockIdx.x == 0) {
        float v = 0.f;
#pragma unroll
        for (int i = tid; i < H_SZ; i += 256) v += bias[i] * shq[i];
        v = warp_sum(v);
        if (lane == 0) redb[grp] = v;
        __syncthreads();
        if (tid < 32) {
            float t = (tid < 8) ? redb[tid] : 0.f;
            t = warp_sum(t);
            if (tid == 0) g_bq[hd] = t;
        }
    }
}

// ---------------- K4: e[hd][s] = ctx[s,:]·u[hd] + bq[hd] ------------------------
// warp-per-row, 8 warps/block, grid = 3*2048/8 = 768
__global__ void k_e(const float* __restrict__ ctxL,
                    const float* __restrict__ ctxR,
                    const float* __restrict__ ctxM) {
    __shared__ float su[C_SZ];
    const int tid  = threadIdx.x;
    const int row  = blockIdx.x * 8 + (tid >> 5);
    const int hd   = row >> 11;
    const int srow = row & (S_SZ - 1);
    for (int i = tid; i < C_SZ; i += blockDim.x) su[i] = g_u[hd][i];
    __syncthreads();

    const float* ctx = (hd == 0) ? ctxL : (hd == 1) ? ctxR : ctxM;
    const float4* c4 = (const float4*)(ctx + (size_t)srow * C_SZ);
    const float4* u4 = (const float4*)su;
    const int lane = tid & 31;
    float s = 0.f;
#pragma unroll 4
    for (int i = lane; i < (C_SZ >> 2); i += 32) s += dot4(c4[i], u4[i]);
    s = warp_sum(s);
    if (lane == 0) g_e[hd][srow] = s + g_bq[hd];
}

// ---------------- K5: fused softmax + weighted column-sum partials --------------
// grid dim3(8 colchunks, NRC rowchunks, 3 heads) = 96 blocks, block 256
__global__ void k_wsum(const float* __restrict__ ctxL,
                       const float* __restrict__ ctxR,
                       const float* __restrict__ ctxM) {
    __shared__ float  sha[S_SZ / NRC];   // weights for this block's 512 rows
    __shared__ float  red[32];
    __shared__ float4 red4[8][32];
    __shared__ float  sM, sZ;
    const int hd  = blockIdx.z;
    const int s0  = blockIdx.y * (S_SZ / NRC);
    const int tid = threadIdx.x;
    const int lane = tid & 31, grp = tid >> 5;

    // --- softmax stats over the full 2048 logits (deterministic) ---
    float le[8], lmax = -1e30f;
#pragma unroll
    for (int k = 0; k < 8; k++) {
        le[k] = g_e[hd][tid + k * 256];
        lmax = fmaxf(lmax, le[k]);
    }
    lmax = warp_max(lmax);
    if (lane == 0) red[grp] = lmax;
    __syncthreads();
    if (tid < 32) {
        float v = (tid < 8) ? red[tid] : -1e30f;
        v = warp_max(v);
        if (tid == 0) sM = v;
    }
    __syncthreads();
    const float M = sM;
    float lsum = 0.f;
#pragma unroll
    for (int k = 0; k < 8; k++) lsum += expf(le[k] - M);
    lsum = warp_sum(lsum);
    __syncthreads();
    if (lane == 0) red[grp] = lsum;
    __syncthreads();
    if (tid < 32) {
        float v = (tid < 8) ? red[tid] : 0.f;
        v = warp_sum(v);
        if (tid == 0) sZ = v;
    }
    __syncthreads();
    const float inv = 1.0f / sZ;
    for (int i = tid; i < S_SZ / NRC; i += 256)
        sha[i] = expf(g_e[hd][s0 + i] - M) * inv;
    __syncthreads();

    // --- weighted column sum over this block's 512 rows ---
    const float* ctx = (hd == 0) ? ctxL : (hd == 1) ? ctxR : ctxM;
    const float4* c4p = (const float4*)ctx;
    const int c4 = blockIdx.x * 32 + lane;
    float4 acc = make_float4(0.f, 0.f, 0.f, 0.f);
#pragma unroll 8
    for (int s = grp; s < S_SZ / NRC; s += 8) {
        float4 v = c4p[(size_t)(s0 + s) * (C_SZ >> 2) + c4];
        float av = sha[s];
        acc.x += v.x * av; acc.y += v.y * av; acc.z += v.z * av; acc.w += v.w * av;
    }
    red4[grp][lane] = acc;
    __syncthreads();
    if (grp == 0) {
        float4 t = red4[0][lane];
#pragma unroll
        for (int k = 1; k < 8; k++) {
            float4 p = red4[k][lane];
            t.x += p.x; t.y += p.y; t.z += p.z; t.w += p.w;
        }
        ((float4*)g_wpart[hd][blockIdx.y])[blockIdx.x * 32 + lane] = t;
    }
}

// ---------------- K6: concat_out = tanh(W_concat @ [q|l|r|m] + b) ---------------
// Sums the wsum partials while staging the input vector. grid 128, block 256.
__device__ __align__(16) float g_concat_out[H_SZ];
__global__ void k_concat_gemv(const float* __restrict__ Wc,
                              const float* __restrict__ bc) {
    __shared__ float shx[4 * H_SZ];
    const int tid = threadIdx.x;
    for (int i = tid; i < 4 * H_SZ; i += 256) {
        float v;
        if (i < H_SZ) v = g_q[i];
        else {
            const int hd = (i >> 10) - 1;
            const int c = i & (H_SZ - 1);
            v = g_wpart[hd][0][c] + g_wpart[hd][1][c] +
                g_wpart[hd][2][c] + g_wpart[hd][3][c];
        }
        shx[i] = v;
    }
    __syncthreads();

    const int row  = blockIdx.x * 8 + (tid >> 5);
    const int lane = tid & 31;
    const float4* a  = (const float4*)(Wc + (size_t)row * 4 * H_SZ);
    const float4* x4 = (const float4*)shx;
    float s = 0.f;
#pragma unroll 4
    for (int i = lane; i < H_SZ; i += 32) s += dot4(a[i], x4[i]);   // 4096/4 f4
    s = warp_sum(s);
    if (lane == 0) g_concat_out[row] = tanhf(s + bc[row]);
}

// ---------------- K7: output = W_out @ concat_out + b_out -----------------------
// warp-per-row, rows=50257; grid 6283, block 256
__global__ void k_out_gemv(const float* __restrict__ Wo,
                           const float* __restrict__ bo,
                           float* __restrict__ out) {
    __shared__ float shx[H_SZ];
    const int tid = threadIdx.x;
    for (int i = tid; i < H_SZ; i += 256) shx[i] = g_concat_out[i];
    __syncthreads();

    const int row = blockIdx.x * 8 + (tid >> 5);
    if (row >= V_SZ) return;
    const int lane = tid & 31;
    const float4* a  = (const float4*)(Wo + (size_t)row * H_SZ);
    const float4* x4 = (const float4*)shx;
    float s = 0.f;
#pragma unroll
    for (int i = lane; i < (H_SZ >> 2); i += 32) s += dot4(a[i], x4[i]);
    s = warp_sum(s);
    if (lane == 0) out[row] = s + bo[row];
}

// ================================================================================
extern "C" void kernel_launch(void* const* d_in, const int* in_sizes, int n_in,
                              void* d_out, int out_size) {
    const int*   input_ids = (const int*)  d_in[0];
    const float* h0        = (const float*)d_in[1];
    const float* c0        = (const float*)d_in[2];
    const float* ctxL      = (const float*)d_in[3];
    const float* ctxR      = (const float*)d_in[4];
    const float* ctxM      = (const float*)d_in[5];
    const float* emb       = (const float*)d_in[6];
    const float* Wih0      = (const float*)d_in[7];
    const float* Whh0      = (const float*)d_in[8];
    const float* bih0      = (const float*)d_in[9];
    const float* bhh0      = (const float*)d_in[10];
    const float* Wih1      = (const float*)d_in[11];
    const float* Whh1      = (const float*)d_in[12];
    const float* bih1      = (const float*)d_in[13];
    const float* bhh1      = (const float*)d_in[14];
    const float* WL        = (const float*)d_in[15];
    const float* bL        = (const float*)d_in[16];
    const float* WR        = (const float*)d_in[17];
    const float* bR        = (const float*)d_in[18];
    const float* WM        = (const float*)d_in[19];
    const float* bM        = (const float*)d_in[20];
    const float* Wc        = (const float*)d_in[21];
    const float* bc        = (const float*)d_in[22];
    const float* Wo        = (const float*)d_in[23];
    const float* bo        = (const float*)d_in[24];

    float* out   = (float*)d_out;            // [V]
    float* h_new = out + V_SZ;               // [2*H]
    float* c_new = out + V_SZ + 2 * H_SZ;    // [2*H]

    // LSTM layer 0 (x = embedding[input_ids]), fused activation
    k_gates_fused<<<128, 256, (E_SZ + H_SZ) * sizeof(float)>>>(
        Wih0, E_SZ, Whh0, bih0, bhh0, emb, input_ids, h0,
        c0, h_new, c_new, 0);

    // LSTM layer 1 (x = h_0), fused activation, writes q
    k_gates_fused<<<128, 256, (H_SZ + H_SZ) * sizeof(float)>>>(
        Wih1, H_SZ, Whh1, bih1, bhh1, h_new, nullptr, h0 + H_SZ,
        c0 + H_SZ, h_new + H_SZ, c_new + H_SZ, 1);

    // u = W^T q and bq = b.q for all 3 heads
    k_u<<<dim3(8, 3), 256>>>(WL, WR, WM, bL, bR, bM);

    // e = ctx.u + bq
    k_e<<<768, 256>>>(ctxL, ctxR, ctxM);

    // fused softmax + weighted column sums (partials)
    k_wsum<<<dim3(8, NRC, 3), 256>>>(ctxL, ctxR, ctxM);

    // concat GEMV (+ partial reduction) with tanh
    k_concat_gemv<<<128, 256>>>(Wc, bc);

    // vocab GEMV
    k_out_gemv<<<(V_SZ + 7) / 8, 256>>>(Wo, bo, out);
}

// round 3
// speedup vs baseline: 1.5721x; 1.5721x over previous
#include <cuda_runtime.h>
#include <math.h>

// Shapes
#define V_SZ 50257
#define E_SZ 512
#define H_SZ 1024
#define C_SZ 1024
#define S_SZ 2048
#define NRC 8               // row-chunks for wsum partials

// ---------------- scratch (device globals) --------------------------------------
__device__ __align__(16) float g_q[H_SZ];               // rnn_output
__device__ __align__(16) float g_u[3][C_SZ];            // W^T q per head
__device__            float g_bq[3];                    // b . q per head
__device__ __align__(16) float g_e[3][S_SZ];            // attention logits
__device__ __align__(16) float g_wpart[3][NRC][C_SZ];   // wsum row-chunk partials
__device__ __align__(16) float g_concat_out[H_SZ];

// ---------------- helpers --------------------------------------------------------
__device__ __forceinline__ float warp_sum(float v) {
#pragma unroll
    for (int o = 16; o; o >>= 1) v += __shfl_xor_sync(0xffffffffu, v, o);
    return v;
}
__device__ __forceinline__ float warp_max(float v) {
#pragma unroll
    for (int o = 16; o; o >>= 1) v = fmaxf(v, __shfl_xor_sync(0xffffffffu, v, o));
    return v;
}
__device__ __forceinline__ float sigf(float x) { return 1.0f / (1.0f + expf(-x)); }
__device__ __forceinline__ float dot4(float4 w, float4 v) {
    return w.x * v.x + w.y * v.y + w.z * v.z + w.w * v.w;
}

// ---------------- K1/K2: LSTM gates (warp-per-row) + fused activation ------------
// grid 128, block 1024 (32 warps). Warp w: gate gi=w>>3, j=blk*8+(w&7).
// After all 32 rows done, threads 0..7 apply the LSTM activation.
__global__ void k_gates(const float* __restrict__ Wih, int lenA,
                        const float* __restrict__ Whh,
                        const float* __restrict__ bih, const float* __restrict__ bhh,
                        const float* __restrict__ xbase, const int* __restrict__ idx,
                        const float* __restrict__ hprev,
                        const float* __restrict__ cprev,
                        float* __restrict__ hout, float* __restrict__ cout,
                        int copy_q) {
    extern __shared__ float sh[];            // lenA + H + 32
    float* gate_sm = sh + lenA + H_SZ;       // [4][8]
    const float* x = idx ? (xbase + (size_t)idx[0] * lenA) : xbase;
    const int tid = threadIdx.x;
    for (int i = tid; i < lenA; i += blockDim.x) sh[i] = x[i];
    for (int i = tid; i < H_SZ; i += blockDim.x) sh[lenA + i] = hprev[i];
    __syncthreads();

    const int w    = tid >> 5;
    const int lane = tid & 31;
    const int gi   = w >> 3;
    const int jj   = w & 7;
    const int j    = blockIdx.x * 8 + jj;
    const int row  = gi * H_SZ + j;

    const float4* a  = (const float4*)(Wih + (size_t)row * lenA);
    const float4* b  = (const float4*)(Whh + (size_t)row * H_SZ);
    const float4* x4 = (const float4*)sh;
    const float4* h4 = (const float4*)(sh + lenA);
    const int nA = lenA >> 2, nH = H_SZ >> 2;

    float s = 0.f;
    for (int i0 = 0; i0 < nA; i0 += 256) {   // batches of 8 independent loads
        float4 wv[8];
#pragma unroll
        for (int k = 0; k < 8; k++) {
            int i = i0 + lane + 32 * k;
            if (i < nA) wv[k] = a[i];
        }
#pragma unroll
        for (int k = 0; k < 8; k++) {
            int i = i0 + lane + 32 * k;
            if (i < nA) s += dot4(wv[k], x4[i]);
        }
    }
    for (int i0 = 0; i0 < nH; i0 += 256) {
        float4 wv[8];
#pragma unroll
        for (int k = 0; k < 8; k++) {
            int i = i0 + lane + 32 * k;
            if (i < nH) wv[k] = b[i];
        }
#pragma unroll
        for (int k = 0; k < 8; k++) {
            int i = i0 + lane + 32 * k;
            if (i < nH) s += dot4(wv[k], h4[i]);
        }
    }
    s = warp_sum(s);
    if (lane == 0) gate_sm[gi * 8 + jj] = s + bih[row] + bhh[row];
    __syncthreads();

    if (tid < 8) {
        const int jo = blockIdx.x * 8 + tid;
        const float ig = sigf (gate_sm[tid]);
        const float fg = sigf (gate_sm[8 + tid]);
        const float gg = tanhf(gate_sm[16 + tid]);
        const float og = sigf (gate_sm[24 + tid]);
        const float c = fg * cprev[jo] + ig * gg;
        const float h = og * tanhf(c);
        cout[jo] = c;
        hout[jo] = h;
        if (copy_q) g_q[jo] = h;
    }
}

// ---------------- K3: u = W^T q (+ bq in chunk 0) --------------------------------
// grid dim3(64, 3): 64 column chunks of 16 floats (4 float4). block 256.
// Thread t: f4-col = t&3, rowgroup = t>>2; accumulates 16 rows, smem tree reduce.
__global__ void k_u(const float* __restrict__ WL,
                    const float* __restrict__ WR,
                    const float* __restrict__ WM,
                    const float* __restrict__ bL,
                    const float* __restrict__ bR,
                    const float* __restrict__ bM) {
    __shared__ float  shq[H_SZ];
    __shared__ float4 red[64][4];
    __shared__ float  redb[8];
    const int hd = blockIdx.y;
    const float* W    = (hd == 0) ? WL : (hd == 1) ? WR : WM;
    const float* bias = (hd == 0) ? bL : (hd == 1) ? bR : bM;
    const int tid = threadIdx.x;
    for (int i = tid; i < H_SZ; i += 256) shq[i] = g_q[i];
    __syncthreads();

    const int col  = tid & 3;
    const int rgrp = tid >> 2;                 // 0..63
    const int c4   = blockIdx.x * 4 + col;     // f4 column index (0..255)
    const float4* W4 = (const float4*)W;

    float4 wv[16];
#pragma unroll
    for (int k = 0; k < 16; k++)
        wv[k] = W4[(size_t)(rgrp + 64 * k) * (C_SZ >> 2) + c4];
    float4 acc = make_float4(0.f, 0.f, 0.f, 0.f);
#pragma unroll
    for (int k = 0; k < 16; k++) {
        float qv = shq[rgrp + 64 * k];
        acc.x += wv[k].x * qv; acc.y += wv[k].y * qv;
        acc.z += wv[k].z * qv; acc.w += wv[k].w * qv;
    }
    red[rgrp][col] = acc;
    __syncthreads();
#pragma unroll
    for (int sdist = 32; sdist >= 1; sdist >>= 1) {
        if (rgrp < sdist) {
            float4 o = red[rgrp + sdist][col];
            float4 m = red[rgrp][col];
            m.x += o.x; m.y += o.y; m.z += o.z; m.w += o.w;
            red[rgrp][col] = m;
        }
        __syncthreads();
    }
    if (tid < 4) ((float4*)g_u[hd])[blockIdx.x * 4 + tid] = red[0][tid];

    // bq = bias . q (chunk 0 only), deterministic fixed-order
    if (blockIdx.x == 0) {
        float v = 0.f;
#pragma unroll
        for (int i = tid; i < H_SZ; i += 256) v += bias[i] * shq[i];
        v = warp_sum(v);
        if ((tid & 31) == 0) redb[tid >> 5] = v;
        __syncthreads();
        if (tid < 32) {
            float t = (tid < 8) ? redb[tid] : 0.f;
            t = warp_sum(t);
            if (tid == 0) g_bq[hd] = t;
        }
    }
}

// ---------------- K4: e[hd][s] = ctx[s,:]·u[hd] + bq[hd] -------------------------
// warp-per-row, 8 warps/block, grid = 3*2048/8 = 768. Batched 8 loads for MLP.
__global__ void k_e(const float* __restrict__ ctxL,
                    const float* __restrict__ ctxR,
                    const float* __restrict__ ctxM) {
    __shared__ float su[C_SZ];
    const int tid  = threadIdx.x;
    const int row  = blockIdx.x * 8 + (tid >> 5);
    const int hd   = row >> 11;
    const int srow = row & (S_SZ - 1);
    for (int i = tid; i < C_SZ; i += blockDim.x) su[i] = g_u[hd][i];
    __syncthreads();

    const float* ctx = (hd == 0) ? ctxL : (hd == 1) ? ctxR : ctxM;
    const float4* c4 = (const float4*)(ctx + (size_t)srow * C_SZ);
    const float4* u4 = (const float4*)su;
    const int lane = tid & 31;

    float4 wv[8];
#pragma unroll
    for (int k = 0; k < 8; k++) wv[k] = c4[lane + 32 * k];   // 256 f4 per row
    float s = 0.f;
#pragma unroll
    for (int k = 0; k < 8; k++) s += dot4(wv[k], u4[lane + 32 * k]);
    s = warp_sum(s);
    if (lane == 0) g_e[hd][srow] = s + g_bq[hd];
}

// ---------------- K5: fused softmax + weighted column-sum partials ---------------
// grid dim3(8 colchunks, NRC rowchunks, 3 heads) = 192 blocks, block 256
__global__ void k_wsum(const float* __restrict__ ctxL,
                       const float* __restrict__ ctxR,
                       const float* __restrict__ ctxM) {
    __shared__ float  sha[S_SZ / NRC];     // 256 weights
    __shared__ float  red[8];
    __shared__ float4 red4[8][32];
    __shared__ float  sM, sZ;
    const int hd  = blockIdx.z;
    const int s0  = blockIdx.y * (S_SZ / NRC);
    const int tid = threadIdx.x;
    const int lane = tid & 31, grp = tid >> 5;

    // softmax stats over full 2048 logits (deterministic fixed order)
    float le[8], lmax = -1e30f;
#pragma unroll
    for (int k = 0; k < 8; k++) {
        le[k] = g_e[hd][tid + k * 256];
        lmax = fmaxf(lmax, le[k]);
    }
    lmax = warp_max(lmax);
    if (lane == 0) red[grp] = lmax;
    __syncthreads();
    if (tid < 32) {
        float v = (tid < 8) ? red[tid] : -1e30f;
        v = warp_max(v);
        if (tid == 0) sM = v;
    }
    __syncthreads();
    const float M = sM;
    float lsum = 0.f;
#pragma unroll
    for (int k = 0; k < 8; k++) lsum += expf(le[k] - M);
    lsum = warp_sum(lsum);
    __syncthreads();
    if (lane == 0) red[grp] = lsum;
    __syncthreads();
    if (tid < 32) {
        float v = (tid < 8) ? red[tid] : 0.f;
        v = warp_sum(v);
        if (tid == 0) sZ = v;
    }
    __syncthreads();
    const float inv = 1.0f / sZ;
    if (tid < S_SZ / NRC) sha[tid] = expf(g_e[hd][s0 + tid] - M) * inv;
    __syncthreads();

    // weighted column sum over this block's 256 rows
    const float* ctx = (hd == 0) ? ctxL : (hd == 1) ? ctxR : ctxM;
    const float4* c4p = (const float4*)ctx;
    const int c4 = blockIdx.x * 32 + lane;
    float4 acc = make_float4(0.f, 0.f, 0.f, 0.f);
    for (int sb = 0; sb < S_SZ / NRC; sb += 64) {            // 8 rows/warp/batch
        float4 v[8];
#pragma unroll
        for (int k = 0; k < 8; k++)
            v[k] = c4p[(size_t)(s0 + sb + grp + 8 * k) * (C_SZ >> 2) + c4];
#pragma unroll
        for (int k = 0; k < 8; k++) {
            float av = sha[sb + grp + 8 * k];
            acc.x += v[k].x * av; acc.y += v[k].y * av;
            acc.z += v[k].z * av; acc.w += v[k].w * av;
        }
    }
    red4[grp][lane] = acc;
    __syncthreads();
    if (grp == 0) {
        float4 t = red4[0][lane];
#pragma unroll
        for (int k = 1; k < 8; k++) {
            float4 p = red4[k][lane];
            t.x += p.x; t.y += p.y; t.z += p.z; t.w += p.w;
        }
        ((float4*)g_wpart[hd][blockIdx.y])[blockIdx.x * 32 + lane] = t;
    }
}

// ---------------- K6: concat_out = tanh(W_concat @ [q|l|r|m] + b) ----------------
// Reduces wsum partials while staging. grid 128, block 256.
__global__ void k_concat_gemv(const float* __restrict__ Wc,
                              const float* __restrict__ bc) {
    __shared__ float shx[4 * H_SZ];
    const int tid = threadIdx.x;
    for (int i = tid; i < 4 * H_SZ; i += 256) {
        float v;
        if (i < H_SZ) v = g_q[i];
        else {
            const int hd = (i >> 10) - 1;
            const int c = i & (H_SZ - 1);
            float s = 0.f;
#pragma unroll
            for (int k = 0; k < NRC; k++) s += g_wpart[hd][k][c];
            v = s;
        }
        shx[i] = v;
    }
    __syncthreads();

    const int row  = blockIdx.x * 8 + (tid >> 5);
    const int lane = tid & 31;
    const float4* a  = (const float4*)(Wc + (size_t)row * 4 * H_SZ);
    const float4* x4 = (const float4*)shx;
    float s = 0.f;
    for (int i0 = 0; i0 < H_SZ; i0 += 256) {     // 1024 f4 total, batches of 8
        float4 wv[8];
#pragma unroll
        for (int k = 0; k < 8; k++) wv[k] = a[i0 + lane + 32 * k];
#pragma unroll
        for (int k = 0; k < 8; k++) s += dot4(wv[k], x4[i0 + lane + 32 * k]);
    }
    s = warp_sum(s);
    if (lane == 0) g_concat_out[row] = tanhf(s + bc[row]);
}

// ---------------- K7: output = W_out @ concat_out + b_out ------------------------
// warp-per-row, rows=50257; grid 6283, block 256
__global__ void k_out_gemv(const float* __restrict__ Wo,
                           const float* __restrict__ bo,
                           float* __restrict__ out) {
    __shared__ float shx[H_SZ];
    const int tid = threadIdx.x;
    for (int i = tid; i < H_SZ; i += 256) shx[i] = g_concat_out[i];
    __syncthreads();

    const int row = blockIdx.x * 8 + (tid >> 5);
    if (row >= V_SZ) return;
    const int lane = tid & 31;
    const float4* a  = (const float4*)(Wo + (size_t)row * H_SZ);
    const float4* x4 = (const float4*)shx;
    float4 wv[8];
#pragma unroll
    for (int k = 0; k < 8; k++) wv[k] = a[lane + 32 * k];    // 256 f4 per row
    float s = 0.f;
#pragma unroll
    for (int k = 0; k < 8; k++) s += dot4(wv[k], x4[lane + 32 * k]);
    s = warp_sum(s);
    if (lane == 0) out[row] = s + bo[row];
}

// ==================================================================================
extern "C" void kernel_launch(void* const* d_in, const int* in_sizes, int n_in,
                              void* d_out, int out_size) {
    const int*   input_ids = (const int*)  d_in[0];
    const float* h0        = (const float*)d_in[1];
    const float* c0        = (const float*)d_in[2];
    const float* ctxL      = (const float*)d_in[3];
    const float* ctxR      = (const float*)d_in[4];
    const float* ctxM      = (const float*)d_in[5];
    const float* emb       = (const float*)d_in[6];
    const float* Wih0      = (const float*)d_in[7];
    const float* Whh0      = (const float*)d_in[8];
    const float* bih0      = (const float*)d_in[9];
    const float* bhh0      = (const float*)d_in[10];
    const float* Wih1      = (const float*)d_in[11];
    const float* Whh1      = (const float*)d_in[12];
    const float* bih1      = (const float*)d_in[13];
    const float* bhh1      = (const float*)d_in[14];
    const float* WL        = (const float*)d_in[15];
    const float* bL        = (const float*)d_in[16];
    const float* WR        = (const float*)d_in[17];
    const float* bR        = (const float*)d_in[18];
    const float* WM        = (const float*)d_in[19];
    const float* bM        = (const float*)d_in[20];
    const float* Wc        = (const float*)d_in[21];
    const float* bc        = (const float*)d_in[22];
    const float* Wo        = (const float*)d_in[23];
    const float* bo        = (const float*)d_in[24];

    float* out   = (float*)d_out;            // [V]
    float* h_new = out + V_SZ;               // [2*H]
    float* c_new = out + V_SZ + 2 * H_SZ;    // [2*H]

    // LSTM layer 0 (x = embedding[input_ids]) with fused activation
    k_gates<<<128, 1024, (E_SZ + H_SZ + 32) * sizeof(float)>>>(
        Wih0, E_SZ, Whh0, bih0, bhh0, emb, input_ids, h0,
        c0, h_new, c_new, 0);

    // LSTM layer 1 (x = h_0) with fused activation, writes q
    k_gates<<<128, 1024, (H_SZ + H_SZ + 32) * sizeof(float)>>>(
        Wih1, H_SZ, Whh1, bih1, bhh1, h_new, nullptr, h0 + H_SZ,
        c0 + H_SZ, h_new + H_SZ, c_new + H_SZ, 1);

    // u = W^T q and bq = b.q (3 heads)
    k_u<<<dim3(64, 3), 256>>>(WL, WR, WM, bL, bR, bM);

    // e = ctx.u + bq
    k_e<<<768, 256>>>(ctxL, ctxR, ctxM);

    // fused softmax + weighted column sums (partials)
    k_wsum<<<dim3(8, NRC, 3), 256>>>(ctxL, ctxR, ctxM);

    // concat GEMV (+ partial reduce) with tanh
    k_concat_gemv<<<128, 256>>>(Wc, bc);

    // vocab GEMV
    k_out_gemv<<<(V_SZ + 7) / 8, 256>>>(Wo, bo, out);
}